// round 4
// baseline (speedup 1.0000x reference)
#include <cuda_runtime.h>
#include <cuda_bf16.h>
#include <cstdint>
#include <cstddef>

#define NR 8192
#define DI 1024
#define DO 4096
#define C  32
#define KSEL 10
#define GAMMA_F 0.01618f

typedef unsigned long long ull;

// ---------------- static device scratch (no allocations allowed) ------------
__device__ __nv_bfloat16 g_xb[(size_t)NR * DI];   // 16 MB bf16 X
__device__ __nv_bfloat16 g_wb[(size_t)DO * DI];   //  8 MB bf16 W
__device__ __nv_bfloat16 g_hb[(size_t)NR * DO];   // 64 MB bf16 h (approx)
__device__ float g_ch[NR * C];                    // refined exact candidate h
__device__ int   g_ci[NR * C];                    // candidate column indices
__device__ float g_cT[NR];                        // certificate threshold

// ---------------- asm helpers ----------------------------------------------
__device__ __forceinline__ uint32_t s2u(const void* p) {
    uint32_t a;
    asm("{ .reg .u64 t; cvta.to.shared.u64 t, %1; cvt.u32.u64 %0, t; }"
        : "=r"(a) : "l"(p));
    return a;
}
__device__ __forceinline__ void cpa16(uint32_t s, const void* g) {
    asm volatile("cp.async.cg.shared.global [%0], [%1], 16;" :: "r"(s), "l"(g));
}
#define CPA_COMMIT() asm volatile("cp.async.commit_group;" ::: "memory")
#define CPA_WAIT1()  asm volatile("cp.async.wait_group 1;" ::: "memory")

__device__ __forceinline__ void ldsm4(uint32_t* r, uint32_t addr) {
    asm volatile("ldmatrix.sync.aligned.m8n8.x4.shared.b16 {%0,%1,%2,%3},[%4];"
                 : "=r"(r[0]), "=r"(r[1]), "=r"(r[2]), "=r"(r[3]) : "r"(addr));
}
__device__ __forceinline__ void mma16816(float* c, const uint32_t* a, const uint32_t* b) {
    asm volatile("mma.sync.aligned.m16n8k16.row.col.f32.bf16.bf16.f32 "
                 "{%0,%1,%2,%3},{%4,%5,%6,%7},{%8,%9},{%0,%1,%2,%3};"
                 : "+f"(c[0]), "+f"(c[1]), "+f"(c[2]), "+f"(c[3])
                 : "r"(a[0]), "r"(a[1]), "r"(a[2]), "r"(a[3]), "r"(b[0]), "r"(b[1]));
}

// ---------------- Phase 0: zero output -------------------------------------
__global__ void zero_kernel(float4* __restrict__ p, int n4) {
    int i = blockIdx.x * blockDim.x + threadIdx.x;
    if (i < n4) p[i] = make_float4(0.f, 0.f, 0.f, 0.f);
}

// ---------------- Phase 0b: fp32 -> bf16 conversion ------------------------
__global__ void cvt_kernel(const float* __restrict__ X, const float* __restrict__ W) {
    const size_t NX4 = (size_t)NR * DI / 4;
    const size_t NW4 = (size_t)DO * DI / 4;
    size_t i = (size_t)blockIdx.x * blockDim.x + threadIdx.x;
    if (i >= NX4 + NW4) return;
    float4 v;
    uint2* dst;
    if (i < NX4) { v = ((const float4*)X)[i]; dst = (uint2*)g_xb + i; }
    else         { v = ((const float4*)W)[i - NX4]; dst = (uint2*)g_wb + (i - NX4); }
    uint32_t lo = (uint32_t)__bfloat16_as_ushort(__float2bfloat16_rn(v.x)) |
                  ((uint32_t)__bfloat16_as_ushort(__float2bfloat16_rn(v.y)) << 16);
    uint32_t hi = (uint32_t)__bfloat16_as_ushort(__float2bfloat16_rn(v.z)) |
                  ((uint32_t)__bfloat16_as_ushort(__float2bfloat16_rn(v.w)) << 16);
    *dst = make_uint2(lo, hi);
}

// ---------------- Phase 1: bf16 HMMA GEMM + bias + leaky -------------------
// 128x128 tile, BK=32, 3-stage cp.async pipeline, 8 warps (2m x 4n),
// warp tile 64x32, smem rows strided 80B (conflict-free ldmatrix).
#define GBK 32
#define ROWB 80
#define TILEB (128 * ROWB)             // 10240
#define STAGEB (2 * TILEB)             // 20480 (A then B)
#define GSTAGES 3
#define OUT_OFF (GSTAGES * STAGEB)     // 61440
#define OUT_STRIDE 136                 // bf16 elems per row (+8 pad)
#define GSMEM (OUT_OFF + 128 * OUT_STRIDE * 2)   // 96256

__global__ void __launch_bounds__(256, 1)
gemm_hmma(const float* __restrict__ bias) {
    extern __shared__ char sm[];
    const uint32_t sb = s2u(sm);
    const int tid = threadIdx.x;
    const int wid = tid >> 5, lane = tid & 31;
    const int row0 = blockIdx.y * 128;
    const int col0 = blockIdx.x * 128;
    const int wm = wid & 1, wn = wid >> 1;

    auto load_stage = [&](int kt, int s) {
        const uint32_t sbase = sb + s * STAGEB;
#pragma unroll
        for (int i = 0; i < 4; ++i) {
            int item = tid + i * 256;          // 0..1023
            int isB = item >> 9;
            int r = (item >> 2) & 127;
            int c = item & 3;
            uint32_t sa = sbase + isB * TILEB + r * ROWB + c * 16;
            const uint4* g = isB
                ? (const uint4*)g_wb + ((size_t)(col0 + r) * (DI / 8) + kt * 4 + c)
                : (const uint4*)g_xb + ((size_t)(row0 + r) * (DI / 8) + kt * 4 + c);
            cpa16(sa, g);
        }
        CPA_COMMIT();
    };

    float acc[4][4][4];
#pragma unroll
    for (int i = 0; i < 4; ++i)
#pragma unroll
        for (int j = 0; j < 4; ++j)
#pragma unroll
            for (int q = 0; q < 4; ++q) acc[i][j][q] = 0.f;

    const int NT = DI / GBK;   // 32
    load_stage(0, 0);
    load_stage(1, 1);
    CPA_WAIT1();
    __syncthreads();

#pragma unroll 1
    for (int kt = 0; kt < NT; ++kt) {
        const uint32_t Ab = sb + (kt % 3) * STAGEB;
        const uint32_t Bb = Ab + TILEB;

        uint32_t a[4][2][4], b[2][2][4];
        const int arow_l = lane & 15;
        const int asel   = (lane >> 4) & 1;
        const int g      = lane >> 3;
#pragma unroll
        for (int im = 0; im < 4; ++im)
#pragma unroll
            for (int ks = 0; ks < 2; ++ks) {
                int arow = wm * 64 + im * 16 + arow_l;
                int ach  = ks * 2 + asel;
                ldsm4(a[im][ks], Ab + arow * ROWB + ach * 16);
            }
#pragma unroll
        for (int p = 0; p < 2; ++p)
#pragma unroll
            for (int ks = 0; ks < 2; ++ks) {
                int blk = p * 2 + (g >> 1);
                int ch  = ks * 2 + (g & 1);
                int nrow = wn * 32 + blk * 8 + (lane & 7);
                ldsm4(b[p][ks], Bb + nrow * ROWB + ch * 16);
            }
#pragma unroll
        for (int im = 0; im < 4; ++im)
#pragma unroll
            for (int p = 0; p < 2; ++p)
#pragma unroll
                for (int ks = 0; ks < 2; ++ks) {
                    mma16816(acc[im][p * 2 + 0], a[im][ks], &b[p][ks][0]);
                    mma16816(acc[im][p * 2 + 1], a[im][ks], &b[p][ks][2]);
                }

        if (kt + 2 < NT) load_stage(kt + 2, (kt + 2) % 3);
        else             CPA_COMMIT();
        CPA_WAIT1();
        __syncthreads();
    }

    // epilogue: bias + leaky -> bf16 -> smem (padded) -> coalesced gmem
#pragma unroll
    for (int im = 0; im < 4; ++im)
#pragma unroll
        for (int in = 0; in < 4; ++in) {
            int rl = wm * 64 + im * 16 + (lane >> 2);
            int cl = wn * 32 + in * 8 + (lane & 3) * 2;
            float b0v = bias[col0 + cl], b1v = bias[col0 + cl + 1];
#pragma unroll
            for (int half = 0; half < 2; ++half) {
                float f0 = acc[im][in][half * 2 + 0] + b0v;
                float f1 = acc[im][in][half * 2 + 1] + b1v;
                f0 = f0 > 0.f ? f0 : 0.01f * f0;
                f1 = f1 > 0.f ? f1 : 0.01f * f1;
                uint32_t pk = (uint32_t)__bfloat16_as_ushort(__float2bfloat16_rn(f0)) |
                              ((uint32_t)__bfloat16_as_ushort(__float2bfloat16_rn(f1)) << 16);
                int r = rl + half * 8;
                *(uint32_t*)(sm + OUT_OFF + (r * OUT_STRIDE + cl) * 2) = pk;
            }
        }
    __syncthreads();
#pragma unroll
    for (int i = 0; i < 8; ++i) {
        int j = tid + i * 256;         // 0..2047
        int r = j >> 4, u = j & 15;
        uint4 v = *(const uint4*)(sm + OUT_OFF + r * OUT_STRIDE * 2 + u * 16);
        *(uint4*)((char*)g_hb + ((size_t)(row0 + r) * DO + col0) * 2 + u * 16) = v;
    }
}

// ---------------- Phase 2: per-row top-32 candidates (16-bit radix) --------
__global__ void __launch_bounds__(256)
cand_kernel() {
    const int row = blockIdx.x;
    const int tid = threadIdx.x;
    __shared__ unsigned short skey[DO];   // 8 KB
    __shared__ int hist[256];
    __shared__ int s_b1, s_need, s_cnt, s_k33;

    const __nv_bfloat16* h = g_hb + (size_t)row * DO;
    for (int i = tid; i < DO / 8; i += 256) {
        uint4 v = ((const uint4*)h)[i];
        uint32_t w[4] = {v.x, v.y, v.z, v.w};
#pragma unroll
        for (int q = 0; q < 4; ++q) {
            uint32_t u0 = w[q] & 0xFFFFu, u1 = w[q] >> 16;
            u0 ^= (u0 & 0x8000u) ? 0xFFFFu : 0x8000u;
            u1 ^= (u1 & 0x8000u) ? 0xFFFFu : 0x8000u;
            skey[i * 8 + q * 2]     = (unsigned short)u0;
            skey[i * 8 + q * 2 + 1] = (unsigned short)u1;
        }
    }
    if (tid == 0) { s_need = C + 1; s_cnt = 0; }
    for (int i = tid; i < 256; i += 256) hist[i] = 0;
    __syncthreads();

    for (int i = tid; i < DO; i += 256) atomicAdd(&hist[skey[i] >> 8], 1);
    __syncthreads();
    if (tid == 0) {
        int need = s_need, acc = 0, b = 255;
        for (;; --b) { acc += hist[b]; if (acc >= need) break; }
        s_need = need - (acc - hist[b]);
        s_b1 = b;
    }
    __syncthreads();
    const int b1 = s_b1;
    for (int i = tid; i < 256; i += 256) hist[i] = 0;
    __syncthreads();
    for (int i = tid; i < DO; i += 256)
        if ((skey[i] >> 8) == b1) atomicAdd(&hist[skey[i] & 255], 1);
    __syncthreads();
    if (tid == 0) {
        int need = s_need, acc = 0, b = 255;
        for (;; --b) { acc += hist[b]; if (acc >= need) break; }
        s_k33 = (b1 << 8) | b;
    }
    __syncthreads();
    const unsigned K33 = (unsigned)s_k33;

    for (int i = tid; i < DO; i += 256) {
        if (skey[i] > K33) {
            int p = atomicAdd(&s_cnt, 1);
            g_ci[row * C + p] = i;
        }
    }
    __syncthreads();
    for (int i = tid; i < DO; i += 256) {
        if (skey[i] == K33) {
            int p = atomicAdd(&s_cnt, 1);
            if (p < C) g_ci[row * C + p] = i;
        }
    }
    __syncthreads();
    if (tid < 32) {   // bitonic sort candidate indices ascending
        int v = g_ci[row * C + tid];
#pragma unroll
        for (int k2 = 2; k2 <= 32; k2 <<= 1)
#pragma unroll
            for (int j = k2 >> 1; j > 0; j >>= 1) {
                int pv = __shfl_xor_sync(0xFFFFFFFFu, v, j);
                bool up = ((tid & k2) == 0);
                bool takemin = (((tid & j) == 0) == up);
                int mn = v < pv ? v : pv, mx = v < pv ? pv : v;
                v = takemin ? mn : mx;
            }
        g_ci[row * C + tid] = v;
        if (tid == 0) {
            unsigned bits = (K33 & 0x8000u) ? (K33 ^ 0x8000u) : (~K33 & 0xFFFFu);
            g_cT[row] = __uint_as_float(bits << 16) + 0.015f;  // + bf16 GEMM err bound
        }
    }
}

// ---------------- Phase 3: compensated-fp32 exact refinement ---------------
__global__ void __launch_bounds__(1024)
refine_kernel(const float* __restrict__ X, const float* __restrict__ W,
              const float* __restrict__ bias) {
    const int row = blockIdx.x, tid = threadIdx.x;
    const int w = tid >> 5, lane = tid & 31;
    __shared__ float sx[DI];
    sx[tid] = X[(size_t)row * DI + tid];
    __syncthreads();

    const int ci = g_ci[row * C + w];
    const float* wr = W + (size_t)ci * DI;
    float hi = 0.f, lo = 0.f;
#pragma unroll 8
    for (int i = 0; i < DI / 32; ++i) {
        int kk = i * 32 + lane;
        float a = sx[kk], b = wr[kk];
        float p  = __fmul_rn(a, b);
        float pe = __fmaf_rn(a, b, -p);
        float t  = __fadd_rn(hi, p);
        float bp = __fsub_rn(t, hi);
        float e  = __fadd_rn(__fsub_rn(hi, __fsub_rn(t, bp)), __fsub_rn(p, bp));
        hi = t;
        lo = __fadd_rn(lo, __fadd_rn(e, pe));
    }
    double d = (double)hi + (double)lo;
#pragma unroll
    for (int off = 16; off; off >>= 1) d += __shfl_xor_sync(0xFFFFFFFFu, d, off);
    if (lane == 0) {
        float hv = (float)d;
        hv = __fadd_rn(hv, bias[ci]);
        hv = (hv > 0.f) ? hv : __fmul_rn(0.01f, hv);
        g_ch[row * C + w] = hv;
    }
}

// ---------------- Phase 4: sequential recurrence (one warp) ----------------
__device__ __noinline__ void fallback_row(const float* __restrict__ X,
                                          const float* __restrict__ W,
                                          const float* __restrict__ bias,
                                          float* __restrict__ out, int t,
                                          int* s_lr, float* s_s,
                                          const float* s_chain, int lane) {
    // exact full-row top-10 (recompute h in fp64 — ~never taken)
    const float* xr = X + (size_t)t * DI;
    for (int col = lane; col < DO; col += 32) {
        const float* wr = W + (size_t)col * DI;
        double d = 0.0;
        for (int k = 0; k < DI; ++k) d += (double)xr[k] * (double)wr[k];
        float hv = __fadd_rn((float)d, bias[col]);
        hv = hv > 0.f ? hv : 0.01f * hv;
        int age = t - s_lr[col] - 1; if (age > 63) age = 63;
        s_s[col] = __fmul_rn(hv, s_chain[age]);
    }
    __syncwarp();
    for (int r = 0; r < KSEL; ++r) {
        float bv = -3.4e38f; int bc = DO;
        for (int col = lane; col < DO; col += 32) {
            float v = s_s[col];
            if (v > bv || (v == bv && col < bc)) { bv = v; bc = col; }
        }
#pragma unroll
        for (int off = 16; off; off >>= 1) {
            float ov = __shfl_xor_sync(0xFFFFFFFFu, bv, off);
            int   oc = __shfl_xor_sync(0xFFFFFFFFu, bc, off);
            if (ov > bv || (ov == bv && oc < bc)) { bv = ov; bc = oc; }
        }
        if (!(bv > 0.f)) break;
        if (lane == 0) {
            out[(size_t)t * DO + bc] = 1.0f;
            s_lr[bc] = t;
            s_s[bc] = -3.4e38f;
        }
        __syncwarp();
    }
    __syncwarp();
}

__global__ void __launch_bounds__(32)
seq_kernel(const float* __restrict__ X, const float* __restrict__ W,
           const float* __restrict__ bias, float* __restrict__ out) {
    __shared__ int   s_lr[DO];
    __shared__ float s_s[DO];
    __shared__ float s_chain[64];
    const int lane = threadIdx.x;

    for (int i = lane; i < DO; i += 32) s_lr[i] = -1000000;
    if (lane == 0) {
        float c = 0.f;
        s_chain[0] = 0.f;
        for (int i = 1; i < 64; ++i) {
            c = fminf(__fadd_rn(c, GAMMA_F), 1.0f);
            s_chain[i] = c;
        }
    }
    __syncwarp();

    float nh = g_ch[lane]; int ni = g_ci[lane]; float nT = g_cT[0];
    for (int t = 0; t < NR; ++t) {
        const float myh = nh; const int myidx = ni; const float T = nT;
        if (t + 1 < NR) {
            nh = g_ch[(t + 1) * C + lane];
            ni = g_ci[(t + 1) * C + lane];
            nT = g_cT[t + 1];
        }
        int lr = s_lr[myidx];
        int age = t - lr - 1; if (age > 63) age = 63;
        const float s = __fmul_rn(myh, s_chain[age]);

        // strict rank among 32 candidates (sorted by column => lane tiebreak)
        int cA = 0, cB = 0;
#pragma unroll
        for (int j = 0; j < 32; j += 2) {
            float s0 = __shfl_sync(0xFFFFFFFFu, s, j);
            float s1 = __shfl_sync(0xFFFFFFFFu, s, j + 1);
            cA += (s0 > s) || (s0 == s && j < lane);
            cB += (s1 > s) || (s1 == s && (j + 1) < lane);
        }
        const int cnt = cA + cB;

        unsigned m9 = __ballot_sync(0xFFFFFFFFu, cnt == 9);
        bool ok = false;
        if (m9) {
            float v10 = __shfl_sync(0xFFFFFFFFu, s, __ffs(m9) - 1);
            ok = (v10 > T + 1e-3f);
        }
        if (ok) {
            if (cnt < KSEL && s > 0.f) {
                out[(size_t)t * DO + myidx] = 1.0f;
                s_lr[myidx] = t;
            }
        } else {
            fallback_row(X, W, bias, out, t, s_lr, s_s, s_chain, lane);
        }
        __syncwarp();
    }
}

// ---------------- launch ----------------------------------------------------
extern "C" void kernel_launch(void* const* d_in, const int* in_sizes, int n_in,
                              void* d_out, int out_size) {
    const float* X    = (const float*)d_in[0];
    const float* W    = (const float*)d_in[1];
    const float* bias = (const float*)d_in[2];
    float* out = (float*)d_out;

    const int n4 = NR * DO / 4;
    zero_kernel<<<(n4 + 255) / 256, 256>>>((float4*)out, n4);

    const size_t ncv = ((size_t)NR * DI + (size_t)DO * DI) / 4;
    cvt_kernel<<<(int)((ncv + 255) / 256), 256>>>(X, W);

    cudaFuncSetAttribute(gemm_hmma, cudaFuncAttributeMaxDynamicSharedMemorySize, GSMEM);
    dim3 gg(DO / 128, NR / 128);
    gemm_hmma<<<gg, 256, GSMEM>>>(bias);

    cand_kernel<<<NR, 256>>>();
    refine_kernel<<<NR, 1024>>>(X, W, bias);
    seq_kernel<<<1, 32>>>(X, W, bias, out);
}

// round 5
// speedup vs baseline: 1.6734x; 1.6734x over previous
#include <cuda_runtime.h>
#include <cuda_bf16.h>
#include <cstdint>
#include <cstddef>

#define NR 8192
#define DI 1024
#define DO 4096
#define C  32
#define KSEL 10
#define GAMMA_F 0.01618f

typedef unsigned long long ull;

// ---------------- static device scratch (no allocations allowed) ------------
__device__ __nv_bfloat16 g_xb[(size_t)NR * DI];   // 16 MB bf16 X
__device__ __nv_bfloat16 g_wb[(size_t)DO * DI];   //  8 MB bf16 W
__device__ __nv_bfloat16 g_hb[(size_t)NR * DO];   // 64 MB bf16 h (approx)
__device__ float g_ch[NR * C];                    // refined exact candidate h
__device__ int   g_ci[NR * C];                    // candidate column indices
__device__ float g_cT[NR];                        // certificate threshold

// ---------------- asm helpers ----------------------------------------------
__device__ __forceinline__ uint32_t s2u(const void* p) {
    uint32_t a;
    asm("{ .reg .u64 t; cvta.to.shared.u64 t, %1; cvt.u32.u64 %0, t; }"
        : "=r"(a) : "l"(p));
    return a;
}
__device__ __forceinline__ void cpa16(uint32_t s, const void* g) {
    asm volatile("cp.async.cg.shared.global [%0], [%1], 16;" :: "r"(s), "l"(g));
}
#define CPA_COMMIT() asm volatile("cp.async.commit_group;" ::: "memory")
#define CPA_WAIT1()  asm volatile("cp.async.wait_group 1;" ::: "memory")

__device__ __forceinline__ void ldsm4(uint32_t* r, uint32_t addr) {
    asm volatile("ldmatrix.sync.aligned.m8n8.x4.shared.b16 {%0,%1,%2,%3},[%4];"
                 : "=r"(r[0]), "=r"(r[1]), "=r"(r[2]), "=r"(r[3]) : "r"(addr));
}
__device__ __forceinline__ void mma16816(float* c, const uint32_t* a, const uint32_t* b) {
    asm volatile("mma.sync.aligned.m16n8k16.row.col.f32.bf16.bf16.f32 "
                 "{%0,%1,%2,%3},{%4,%5,%6,%7},{%8,%9},{%0,%1,%2,%3};"
                 : "+f"(c[0]), "+f"(c[1]), "+f"(c[2]), "+f"(c[3])
                 : "r"(a[0]), "r"(a[1]), "r"(a[2]), "r"(a[3]), "r"(b[0]), "r"(b[1]));
}

// ---------------- Phase 0: zero output -------------------------------------
__global__ void zero_kernel(float4* __restrict__ p, int n4) {
    int i = blockIdx.x * blockDim.x + threadIdx.x;
    if (i < n4) p[i] = make_float4(0.f, 0.f, 0.f, 0.f);
}

// ---------------- Phase 0b: fp32 -> bf16 conversion ------------------------
__global__ void cvt_kernel(const float* __restrict__ X, const float* __restrict__ W) {
    const size_t NX4 = (size_t)NR * DI / 4;
    const size_t NW4 = (size_t)DO * DI / 4;
    size_t i = (size_t)blockIdx.x * blockDim.x + threadIdx.x;
    if (i >= NX4 + NW4) return;
    float4 v;
    uint2* dst;
    if (i < NX4) { v = ((const float4*)X)[i]; dst = (uint2*)g_xb + i; }
    else         { v = ((const float4*)W)[i - NX4]; dst = (uint2*)g_wb + (i - NX4); }
    uint32_t lo = (uint32_t)__bfloat16_as_ushort(__float2bfloat16_rn(v.x)) |
                  ((uint32_t)__bfloat16_as_ushort(__float2bfloat16_rn(v.y)) << 16);
    uint32_t hi = (uint32_t)__bfloat16_as_ushort(__float2bfloat16_rn(v.z)) |
                  ((uint32_t)__bfloat16_as_ushort(__float2bfloat16_rn(v.w)) << 16);
    *dst = make_uint2(lo, hi);
}

// ---------------- Phase 1: bf16 HMMA GEMM + bias + leaky -------------------
#define GBK 32
#define ROWB 80
#define TILEB (128 * ROWB)
#define STAGEB (2 * TILEB)
#define GSTAGES 3
#define OUT_OFF (GSTAGES * STAGEB)
#define OUT_STRIDE 136
#define GSMEM (OUT_OFF + 128 * OUT_STRIDE * 2)

__global__ void __launch_bounds__(256, 1)
gemm_hmma(const float* __restrict__ bias) {
    extern __shared__ char sm[];
    const uint32_t sb = s2u(sm);
    const int tid = threadIdx.x;
    const int wid = tid >> 5, lane = tid & 31;
    const int row0 = blockIdx.y * 128;
    const int col0 = blockIdx.x * 128;
    const int wm = wid & 1, wn = wid >> 1;

    auto load_stage = [&](int kt, int s) {
        const uint32_t sbase = sb + s * STAGEB;
#pragma unroll
        for (int i = 0; i < 4; ++i) {
            int item = tid + i * 256;
            int isB = item >> 9;
            int r = (item >> 2) & 127;
            int c = item & 3;
            uint32_t sa = sbase + isB * TILEB + r * ROWB + c * 16;
            const uint4* g = isB
                ? (const uint4*)g_wb + ((size_t)(col0 + r) * (DI / 8) + kt * 4 + c)
                : (const uint4*)g_xb + ((size_t)(row0 + r) * (DI / 8) + kt * 4 + c);
            cpa16(sa, g);
        }
        CPA_COMMIT();
    };

    float acc[4][4][4];
#pragma unroll
    for (int i = 0; i < 4; ++i)
#pragma unroll
        for (int j = 0; j < 4; ++j)
#pragma unroll
            for (int q = 0; q < 4; ++q) acc[i][j][q] = 0.f;

    const int NT = DI / GBK;
    load_stage(0, 0);
    load_stage(1, 1);
    CPA_WAIT1();
    __syncthreads();

#pragma unroll 1
    for (int kt = 0; kt < NT; ++kt) {
        const uint32_t Ab = sb + (kt % 3) * STAGEB;
        const uint32_t Bb = Ab + TILEB;

        uint32_t a[4][2][4], b[2][2][4];
        const int arow_l = lane & 15;
        const int asel   = (lane >> 4) & 1;
        const int g      = lane >> 3;
#pragma unroll
        for (int im = 0; im < 4; ++im)
#pragma unroll
            for (int ks = 0; ks < 2; ++ks) {
                int arow = wm * 64 + im * 16 + arow_l;
                int ach  = ks * 2 + asel;
                ldsm4(a[im][ks], Ab + arow * ROWB + ach * 16);
            }
#pragma unroll
        for (int p = 0; p < 2; ++p)
#pragma unroll
            for (int ks = 0; ks < 2; ++ks) {
                int blk = p * 2 + (g >> 1);
                int ch  = ks * 2 + (g & 1);
                int nrow = wn * 32 + blk * 8 + (lane & 7);
                ldsm4(b[p][ks], Bb + nrow * ROWB + ch * 16);
            }
#pragma unroll
        for (int im = 0; im < 4; ++im)
#pragma unroll
            for (int p = 0; p < 2; ++p)
#pragma unroll
                for (int ks = 0; ks < 2; ++ks) {
                    mma16816(acc[im][p * 2 + 0], a[im][ks], &b[p][ks][0]);
                    mma16816(acc[im][p * 2 + 1], a[im][ks], &b[p][ks][2]);
                }

        if (kt + 2 < NT) load_stage(kt + 2, (kt + 2) % 3);
        else             CPA_COMMIT();
        CPA_WAIT1();
        __syncthreads();
    }

#pragma unroll
    for (int im = 0; im < 4; ++im)
#pragma unroll
        for (int in = 0; in < 4; ++in) {
            int rl = wm * 64 + im * 16 + (lane >> 2);
            int cl = wn * 32 + in * 8 + (lane & 3) * 2;
            float b0v = bias[col0 + cl], b1v = bias[col0 + cl + 1];
#pragma unroll
            for (int half = 0; half < 2; ++half) {
                float f0 = acc[im][in][half * 2 + 0] + b0v;
                float f1 = acc[im][in][half * 2 + 1] + b1v;
                f0 = f0 > 0.f ? f0 : 0.01f * f0;
                f1 = f1 > 0.f ? f1 : 0.01f * f1;
                uint32_t pk = (uint32_t)__bfloat16_as_ushort(__float2bfloat16_rn(f0)) |
                              ((uint32_t)__bfloat16_as_ushort(__float2bfloat16_rn(f1)) << 16);
                int r = rl + half * 8;
                *(uint32_t*)(sm + OUT_OFF + (r * OUT_STRIDE + cl) * 2) = pk;
            }
        }
    __syncthreads();
#pragma unroll
    for (int i = 0; i < 8; ++i) {
        int j = tid + i * 256;
        int r = j >> 4, u = j & 15;
        uint4 v = *(const uint4*)(sm + OUT_OFF + r * OUT_STRIDE * 2 + u * 16);
        *(uint4*)((char*)g_hb + ((size_t)(row0 + r) * DO + col0) * 2 + u * 16) = v;
    }
}

// ---------------- Phase 2: per-row top-32 candidates (16-bit radix) --------
__global__ void __launch_bounds__(256)
cand_kernel() {
    const int row = blockIdx.x;
    const int tid = threadIdx.x;
    __shared__ unsigned short skey[DO];
    __shared__ int hist[256];
    __shared__ int s_b1, s_need, s_cnt, s_k33;

    const __nv_bfloat16* h = g_hb + (size_t)row * DO;
    for (int i = tid; i < DO / 8; i += 256) {
        uint4 v = ((const uint4*)h)[i];
        uint32_t w[4] = {v.x, v.y, v.z, v.w};
#pragma unroll
        for (int q = 0; q < 4; ++q) {
            uint32_t u0 = w[q] & 0xFFFFu, u1 = w[q] >> 16;
            u0 ^= (u0 & 0x8000u) ? 0xFFFFu : 0x8000u;
            u1 ^= (u1 & 0x8000u) ? 0xFFFFu : 0x8000u;
            skey[i * 8 + q * 2]     = (unsigned short)u0;
            skey[i * 8 + q * 2 + 1] = (unsigned short)u1;
        }
    }
    if (tid == 0) { s_need = C + 1; s_cnt = 0; }
    for (int i = tid; i < 256; i += 256) hist[i] = 0;
    __syncthreads();

    for (int i = tid; i < DO; i += 256) atomicAdd(&hist[skey[i] >> 8], 1);
    __syncthreads();
    if (tid == 0) {
        int need = s_need, acc = 0, b = 255;
        for (;; --b) { acc += hist[b]; if (acc >= need) break; }
        s_need = need - (acc - hist[b]);
        s_b1 = b;
    }
    __syncthreads();
    const int b1 = s_b1;
    for (int i = tid; i < 256; i += 256) hist[i] = 0;
    __syncthreads();
    for (int i = tid; i < DO; i += 256)
        if ((skey[i] >> 8) == b1) atomicAdd(&hist[skey[i] & 255], 1);
    __syncthreads();
    if (tid == 0) {
        int need = s_need, acc = 0, b = 255;
        for (;; --b) { acc += hist[b]; if (acc >= need) break; }
        s_k33 = (b1 << 8) | b;
    }
    __syncthreads();
    const unsigned K33 = (unsigned)s_k33;

    for (int i = tid; i < DO; i += 256) {
        if (skey[i] > K33) {
            int p = atomicAdd(&s_cnt, 1);
            g_ci[row * C + p] = i;
        }
    }
    __syncthreads();
    for (int i = tid; i < DO; i += 256) {
        if (skey[i] == K33) {
            int p = atomicAdd(&s_cnt, 1);
            if (p < C) g_ci[row * C + p] = i;
        }
    }
    __syncthreads();
    if (tid < 32) {   // bitonic sort candidate indices ascending
        int v = g_ci[row * C + tid];
#pragma unroll
        for (int k2 = 2; k2 <= 32; k2 <<= 1)
#pragma unroll
            for (int j = k2 >> 1; j > 0; j >>= 1) {
                int pv = __shfl_xor_sync(0xFFFFFFFFu, v, j);
                bool up = ((tid & k2) == 0);
                bool takemin = (((tid & j) == 0) == up);
                int mn = v < pv ? v : pv, mx = v < pv ? pv : v;
                v = takemin ? mn : mx;
            }
        g_ci[row * C + tid] = v;
        if (tid == 0) {
            unsigned bits = (K33 & 0x8000u) ? (K33 ^ 0x8000u) : (~K33 & 0xFFFFu);
            g_cT[row] = __uint_as_float(bits << 16) + 0.015f;
        }
    }
}

// ---------------- Phase 3: compensated-fp32 exact refinement ---------------
__global__ void __launch_bounds__(1024)
refine_kernel(const float* __restrict__ X, const float* __restrict__ W,
              const float* __restrict__ bias) {
    const int row = blockIdx.x, tid = threadIdx.x;
    const int w = tid >> 5, lane = tid & 31;
    __shared__ float sx[DI];
    sx[tid] = X[(size_t)row * DI + tid];
    __syncthreads();

    const int ci = g_ci[row * C + w];
    const float* wr = W + (size_t)ci * DI;
    float hi = 0.f, lo = 0.f;
#pragma unroll 8
    for (int i = 0; i < DI / 32; ++i) {
        int kk = i * 32 + lane;
        float a = sx[kk], b = wr[kk];
        float p  = __fmul_rn(a, b);
        float pe = __fmaf_rn(a, b, -p);
        float t  = __fadd_rn(hi, p);
        float bp = __fsub_rn(t, hi);
        float e  = __fadd_rn(__fsub_rn(hi, __fsub_rn(t, bp)), __fsub_rn(p, bp));
        hi = t;
        lo = __fadd_rn(lo, __fadd_rn(e, pe));
    }
    double d = (double)hi + (double)lo;
#pragma unroll
    for (int off = 16; off; off >>= 1) d += __shfl_xor_sync(0xFFFFFFFFu, d, off);
    if (lane == 0) {
        float hv = (float)d;
        hv = __fadd_rn(hv, bias[ci]);
        hv = (hv > 0.f) ? hv : __fmul_rn(0.01f, hv);
        g_ch[row * C + w] = hv;
    }
}

// ---------------- Phase 4: sequential recurrence (one warp) ----------------
#define FB_CAP 512

__device__ __forceinline__ float exact_col(const float* __restrict__ sx,
                                           const float* __restrict__ W,
                                           const float* __restrict__ bias,
                                           int col) {
    const float* wr = W + (size_t)col * DI;
    double d0 = 0, d1 = 0, d2 = 0, d3 = 0;
#pragma unroll 4
    for (int k = 0; k < DI; k += 4) {
        d0 = fma((double)sx[k + 0], (double)wr[k + 0], d0);
        d1 = fma((double)sx[k + 1], (double)wr[k + 1], d1);
        d2 = fma((double)sx[k + 2], (double)wr[k + 2], d2);
        d3 = fma((double)sx[k + 3], (double)wr[k + 3], d3);
    }
    float hv = (float)((d0 + d1) + (d2 + d3));
    hv = __fadd_rn(hv, bias[col]);
    return hv > 0.f ? hv : __fmul_rn(0.01f, hv);
}

__device__ __noinline__ void fallback_row(const float* __restrict__ X,
                                          const float* __restrict__ W,
                                          const float* __restrict__ bias,
                                          float* __restrict__ out, int t,
                                          int* s_lr, float* s_s, float* s_x,
                                          int* s_cand, float* s_cs, int* s_nc,
                                          const float* s_chain, int lane) {
    // 1) approx s from bf16 h for all columns
    const __nv_bfloat16* hb = g_hb + (size_t)t * DO;
    for (int col = lane; col < DO; col += 32) {
        int age = t - s_lr[col] - 1; if (age > 63) age = 63;
        s_s[col] = __bfloat162float(hb[col]) * s_chain[age];
    }
    if (lane == 0) *s_nc = 0;
    __syncwarp();

    // 2) 10th largest approx s
    float fs[DO / 32];
#pragma unroll 4
    for (int i = 0; i < DO / 32; ++i) fs[i] = s_s[i * 32 + lane];
    float t10b = -3.4e38f;
    for (int r = 0; r < KSEL; ++r) {
        float bv = -3.4e38f; int bi = 0;
#pragma unroll 4
        for (int i = 0; i < DO / 32; ++i)
            if (fs[i] > bv) { bv = fs[i]; bi = i; }
        float rv = bv;
#pragma unroll
        for (int off = 16; off; off >>= 1)
            rv = fmaxf(rv, __shfl_xor_sync(0xFFFFFFFFu, rv, off));
        t10b = rv;
        unsigned m = __ballot_sync(0xFFFFFFFFu, bv == rv);
        if (lane == __ffs(m) - 1) fs[bi] = -3.4e38f;
    }

    // 3) sound candidate set: |s_exact - s_approx| <= ~0.021 < 0.05/2
    const float thr = t10b - 0.05f;
    for (int col = lane; col < DO; col += 32) {
        if (s_s[col] >= thr) {
            int p = atomicAdd(s_nc, 1);
            if (p < FB_CAP) s_cand[p] = col;
        }
    }
    __syncwarp();
    const int nc = *s_nc;

    // X row to shared
    for (int i = lane; i < DI; i += 32) s_x[i] = X[(size_t)t * DI + i];
    __syncwarp();

    if (nc <= FB_CAP) {
        // 4) exact refine candidates only
        for (int c = lane; c < nc; c += 32) {
            int col = s_cand[c];
            float hv = exact_col(s_x, W, bias, col);
            int age = t - s_lr[col] - 1; if (age > 63) age = 63;
            s_cs[c] = __fmul_rn(hv, s_chain[age]);
        }
        __syncwarp();
        // 5) exact top-10 (value desc, column asc tiebreak)
        for (int r = 0; r < KSEL; ++r) {
            float bv = -3.4e38f; int bcol = 1 << 30, bslot = 0;
            for (int c = lane; c < nc; c += 32) {
                float v = s_cs[c]; int col = s_cand[c];
                if (v > bv || (v == bv && col < bcol)) { bv = v; bcol = col; bslot = c; }
            }
#pragma unroll
            for (int off = 16; off; off >>= 1) {
                float ov = __shfl_xor_sync(0xFFFFFFFFu, bv, off);
                int   oc = __shfl_xor_sync(0xFFFFFFFFu, bcol, off);
                int   os = __shfl_xor_sync(0xFFFFFFFFu, bslot, off);
                if (ov > bv || (ov == bv && oc < bcol)) { bv = ov; bcol = oc; bslot = os; }
            }
            if (!(bv > 0.f)) break;
            if (lane == 0) {
                out[(size_t)t * DO + bcol] = 1.0f;
                s_lr[bcol] = t;
                s_cs[bslot] = -3.4e38f;
            }
            __syncwarp();
        }
    } else {
        // pathological: exact everything (never expected)
        for (int col = lane; col < DO; col += 32) {
            float hv = exact_col(s_x, W, bias, col);
            int age = t - s_lr[col] - 1; if (age > 63) age = 63;
            s_s[col] = __fmul_rn(hv, s_chain[age]);
        }
        __syncwarp();
        for (int r = 0; r < KSEL; ++r) {
            float bv = -3.4e38f; int bcol = 1 << 30;
            for (int col = lane; col < DO; col += 32) {
                float v = s_s[col];
                if (v > bv || (v == bv && col < bcol)) { bv = v; bcol = col; }
            }
#pragma unroll
            for (int off = 16; off; off >>= 1) {
                float ov = __shfl_xor_sync(0xFFFFFFFFu, bv, off);
                int   oc = __shfl_xor_sync(0xFFFFFFFFu, bcol, off);
                if (ov > bv || (ov == bv && oc < bcol)) { bv = ov; bcol = oc; }
            }
            if (!(bv > 0.f)) break;
            if (lane == 0) {
                out[(size_t)t * DO + bcol] = 1.0f;
                s_lr[bcol] = t;
                s_s[bcol] = -3.4e38f;
            }
            __syncwarp();
        }
    }
    __syncwarp();
}

__global__ void __launch_bounds__(32)
seq_kernel(const float* __restrict__ X, const float* __restrict__ W,
           const float* __restrict__ bias, float* __restrict__ out) {
    __shared__ int   s_lr[DO];
    __shared__ float s_s[DO];
    __shared__ float s_x[DI];
    __shared__ int   s_cand[FB_CAP];
    __shared__ float s_cs[FB_CAP];
    __shared__ float s_chain[64];
    __shared__ int   s_nc;
    const int lane = threadIdx.x;

    for (int i = lane; i < DO; i += 32) s_lr[i] = -1000000;
    if (lane == 0) {
        float c = 0.f;
        s_chain[0] = 0.f;
        for (int i = 1; i < 64; ++i) {
            c = fminf(__fadd_rn(c, GAMMA_F), 1.0f);
            s_chain[i] = c;
        }
    }
    __syncwarp();

    float nh = g_ch[lane]; int ni = g_ci[lane]; float nT = g_cT[0];
    for (int t = 0; t < NR; ++t) {
        const float myh = nh; const int myidx = ni; const float T = nT;
        if (t + 1 < NR) {
            nh = g_ch[(t + 1) * C + lane];
            ni = g_ci[(t + 1) * C + lane];
            nT = g_cT[t + 1];
        }
        int lr = s_lr[myidx];
        int age = t - lr - 1; if (age > 63) age = 63;
        const float s = __fmul_rn(myh, s_chain[age]);

        // strict rank among 32 candidates (sorted by column => lane tiebreak)
        int cA = 0, cB = 0;
#pragma unroll
        for (int j = 0; j < 32; j += 2) {
            float s0 = __shfl_sync(0xFFFFFFFFu, s, j);
            float s1 = __shfl_sync(0xFFFFFFFFu, s, j + 1);
            cA += (s0 > s) || (s0 == s && j < lane);
            cB += (s1 > s) || (s1 == s && (j + 1) < lane);
        }
        const int cnt = cA + cB;

        unsigned m9 = __ballot_sync(0xFFFFFFFFu, cnt == 9);
        bool ok = false;
        if (m9) {
            float v10 = __shfl_sync(0xFFFFFFFFu, s, __ffs(m9) - 1);
            ok = (v10 > T + 0.005f);   // total margin 0.020 over bf16 33rd
        }
        if (ok) {
            if (cnt < KSEL && s > 0.f) {
                out[(size_t)t * DO + myidx] = 1.0f;
                s_lr[myidx] = t;
            }
        } else {
            fallback_row(X, W, bias, out, t, s_lr, s_s, s_x,
                         s_cand, s_cs, &s_nc, s_chain, lane);
        }
        __syncwarp();
    }
}

// ---------------- launch ----------------------------------------------------
extern "C" void kernel_launch(void* const* d_in, const int* in_sizes, int n_in,
                              void* d_out, int out_size) {
    const float* X    = (const float*)d_in[0];
    const float* W    = (const float*)d_in[1];
    const float* bias = (const float*)d_in[2];
    float* out = (float*)d_out;

    const int n4 = NR * DO / 4;
    zero_kernel<<<(n4 + 255) / 256, 256>>>((float4*)out, n4);

    const size_t ncv = ((size_t)NR * DI + (size_t)DO * DI) / 4;
    cvt_kernel<<<(int)((ncv + 255) / 256), 256>>>(X, W);

    cudaFuncSetAttribute(gemm_hmma, cudaFuncAttributeMaxDynamicSharedMemorySize, GSMEM);
    dim3 gg(DO / 128, NR / 128);
    gemm_hmma<<<gg, 256, GSMEM>>>(bias);

    cand_kernel<<<NR, 256>>>();
    refine_kernel<<<NR, 1024>>>(X, W, bias);
    seq_kernel<<<1, 32>>>(X, W, bias, out);
}